// round 13
// baseline (speedup 1.0000x reference)
#include <cuda_runtime.h>
#include <cstdint>

#define B_ 256
#define T_ 512
#define D_ 128
#define H_ 128
#define G_ 384          // 3H, gate order z|r|h
#define BT_ (B_*T_)

__device__ float g_xp[(size_t)BT_ * G_];   // 201 MB scratch
__device__ float g_h0[(size_t)BT_ * H_];   // 67 MB scratch

typedef unsigned long long u64;

static __device__ __forceinline__ u64 pack2(float a, float b) {
    u64 r; asm("mov.b64 %0, {%1, %2};" : "=l"(r) : "f"(a), "f"(b)); return r;
}
static __device__ __forceinline__ void unpack2(u64 v, float &a, float &b) {
    asm("mov.b64 {%0, %1}, %2;" : "=f"(a), "=f"(b) : "l"(v));
}
static __device__ __forceinline__ u64 fma2(u64 a, u64 b, u64 c) {
    u64 d; asm("fma.rn.f32x2 %0, %1, %2, %3;" : "=l"(d) : "l"(a), "l"(b), "l"(c)); return d;
}
// MUFU tanh (sm_75+ PTX, not arch-'a' gated)
static __device__ __forceinline__ float tanh_mufu(float x) {
    float r; asm("tanh.approx.f32 %0, %1;" : "=f"(r) : "f"(x)); return r;
}
static __device__ __forceinline__ float sig_mufu(float x) {
    return fmaf(0.5f, tanh_mufu(0.5f * x), 0.5f);
}

// ---------------------------------------------------------------------------
// Projection — VERBATIM R12 (measured ~286us/layer): 256 threads; thread
// (u, kg) owns gate-triple columns {u, u+128, u+256} over its 64-k half.
// Per row: 16 broadcast LDS.128 -> 96 FFMA2 -> 3 shfl.xor(16) -> lane<16 STG.
// ---------------------------------------------------------------------------
__global__ __launch_bounds__(256, 1)
void proj_kernel(const float* __restrict__ x, const float* __restrict__ W,
                 const float* __restrict__ bin, float* __restrict__ out,
                 int rows_per_block)
{
    __shared__ __align__(16) float x_sm[2][8][D_];
    const int tid  = threadIdx.x;
    const int lane = tid & 31;
    const int kg   = lane >> 4;
    const int u    = (tid >> 5) * 16 + (lane & 15);
    const int kb   = kg * 64;

    u64 w[3][32];
#pragma unroll
    for (int i = 0; i < 32; i++)
#pragma unroll
        for (int c = 0; c < 3; c++)
            w[c][i] = pack2(W[(kb + 2*i) * G_ + u + c*128],
                            W[(kb + 2*i + 1) * G_ + u + c*128]);
    const float b0 = bin[u];
    const float b1 = bin[u + 128];
    const float b2 = bin[u + 256];

    const int row0 = blockIdx.x * rows_per_block;
    ((float4*)&x_sm[0][0][0])[tid] = ((const float4*)(x + (size_t)row0 * D_))[tid];
    __syncthreads();

    const int iters = rows_per_block / 8;
    int buf = 0;
    for (int it = 0; it < iters; it++) {
        const int rbase = row0 + it * 8;
        float4 nx;
        const bool pre = (it + 1 < iters);
        if (pre)
            nx = ((const float4*)(x + (size_t)(rbase + 8) * D_))[tid];

#pragma unroll
        for (int r = 0; r < 8; r++) {
            u64 a0 = 0, a1 = 0, a2 = 0;
            const float* xs = &x_sm[buf][r][kb];
#pragma unroll
            for (int i2 = 0; i2 < 16; i2++) {
                ulonglong2 hv = *(const ulonglong2*)&xs[4*i2];
                a0 = fma2(hv.x, w[0][2*i2],     a0);
                a0 = fma2(hv.y, w[0][2*i2 + 1], a0);
                a1 = fma2(hv.x, w[1][2*i2],     a1);
                a1 = fma2(hv.y, w[1][2*i2 + 1], a1);
                a2 = fma2(hv.x, w[2][2*i2],     a2);
                a2 = fma2(hv.y, w[2][2*i2 + 1], a2);
            }
            float pa, pb, pc, pd, pe, pf;
            unpack2(a0, pa, pb);
            unpack2(a1, pc, pd);
            unpack2(a2, pe, pf);
            float s0 = pa + pb, s1 = pc + pd, s2 = pe + pf;
            s0 += __shfl_xor_sync(0xffffffffu, s0, 16);
            s1 += __shfl_xor_sync(0xffffffffu, s1, 16);
            s2 += __shfl_xor_sync(0xffffffffu, s2, 16);
            if (lane < 16) {
                float* o = out + (size_t)(rbase + r) * G_;
                o[u]       = s0 + b0;
                o[u + 128] = s1 + b1;
                o[u + 256] = s2 + b2;
            }
        }
        if (pre)
            ((float4*)&x_sm[buf ^ 1][0][0])[tid] = nx;
        __syncthreads();
        buf ^= 1;
    }
}

// ---------------------------------------------------------------------------
// GRU scan, phase-skewed: 2*T+1 phases. Phase p:
//   gates (tid<128): consume rec_sm[q] (q = row (p-1)&1, t = (p-1)>>1) written
//     last phase; MUFU chain; write h_sm[q] + out. Issued BEFORE the matvec so
//     its latencies hide under FFMA2 issue (warps 4-7 have no gate work and
//     feed the fma pipe continuously — one per SMSP).
//   matvec (all 256): row rm = p&1, t = p>>1, reading h_sm[rm] (written p-1);
//     3 accumulators; 3x shfl.xor(16); lane<16 -> rec_sm[rm].
// One barrier per phase. rec/h row-halves never conflict within a phase.
// ---------------------------------------------------------------------------
__global__ __launch_bounds__(256, 1)
void gru_scan(const float* __restrict__ U, const float* __restrict__ brec,
              const float* __restrict__ xp, float* __restrict__ out)
{
    __shared__ __align__(16) float h_sm[2][2][68];   // [row][kg][64 used]
    __shared__ float rec_sm[2][G_];                  // [row][j] raw sums
    const int tid  = threadIdx.x;
    const int lane = tid & 31;
    const int kg   = lane >> 4;
    const int u    = (tid >> 5) * 16 + (lane & 15);
    const int kb   = kg * 64;

    u64 w[3][32];
#pragma unroll
    for (int i = 0; i < 32; i++)
#pragma unroll
        for (int c = 0; c < 3; c++)
            w[c][i] = pack2(U[(kb + 2*i) * G_ + u + c*128],
                            U[(kb + 2*i + 1) * G_ + u + c*128]);

    const int b0 = blockIdx.x * 2;

    // ---- gate role state (tid < 128): unit gu, both rows alternately ----
    const bool gact = tid < 128;
    const int  gu   = tid & 127;
    float gbz = 0.f, gbr = 0.f, gbh = 0.f;
    const float* gxr0 = xp + (size_t)b0 * T_ * G_;
    const float* gxr1 = xp + (size_t)(b0 + 1) * T_ * G_;
    float* gor0 = out + (size_t)b0 * T_ * H_;
    float* gor1 = out + (size_t)(b0 + 1) * T_ * H_;
    float xzv[2], xrv[2], xhv[2], hpv[2];
    if (gact) {
        gbz = brec[gu]; gbr = brec[gu + 128]; gbh = brec[gu + 256];
        xzv[0] = gxr0[gu]; xrv[0] = gxr0[gu + 128]; xhv[0] = gxr0[gu + 256];
        xzv[1] = gxr1[gu]; xrv[1] = gxr1[gu + 128]; xhv[1] = gxr1[gu + 256];
        hpv[0] = 0.f; hpv[1] = 0.f;
        h_sm[0][gu >> 6][gu & 63] = 0.0f;
        h_sm[1][gu >> 6][gu & 63] = 0.0f;
    }
    __syncthreads();

    for (int p = 0; p <= 2 * T_; p++) {
        const int rm = p & 1;            // matvec row
        const int q  = rm ^ 1;           // gate row (= (p-1)&1 for p>=1)
        const int te = (p - 1) >> 1;     // gate timestep
        const bool do_mv = p < 2 * T_;
        const bool ga    = gact && (p >= 1);

        // ---- gate loads + xp prefetch (issued first, latency hidden) ----
        float rz = 0.f, rr = 0.f, rh = 0.f;
        float nxz = 0.f, nxr = 0.f, nxh = 0.f;
        if (ga) {
            rz = rec_sm[q][gu];
            rr = rec_sm[q][gu + 128];
            rh = rec_sm[q][gu + 256];
            if (te + 1 < T_) {
                const float* xn = (q ? gxr1 : gxr0) + (size_t)(te + 1) * G_;
                nxz = xn[gu]; nxr = xn[gu + 128]; nxh = xn[gu + 256];
            }
        }

        // ---- matvec: row rm, 3 gate columns over own k-half ----
        if (do_mv) {
            u64 a0 = 0, a1 = 0, a2 = 0;
            const float* hs = &h_sm[rm][kg][0];
#pragma unroll
            for (int i2 = 0; i2 < 16; i2++) {
                ulonglong2 hv = *(const ulonglong2*)&hs[4*i2];
                a0 = fma2(hv.x, w[0][2*i2],     a0);
                a0 = fma2(hv.y, w[0][2*i2 + 1], a0);
                a1 = fma2(hv.x, w[1][2*i2],     a1);
                a1 = fma2(hv.y, w[1][2*i2 + 1], a1);
                a2 = fma2(hv.x, w[2][2*i2],     a2);
                a2 = fma2(hv.y, w[2][2*i2 + 1], a2);
            }
            float pa, pb, pc, pd, pe, pf;
            unpack2(a0, pa, pb);
            unpack2(a1, pc, pd);
            unpack2(a2, pe, pf);
            float s0 = pa + pb, s1 = pc + pd, s2 = pe + pf;
            s0 += __shfl_xor_sync(0xffffffffu, s0, 16);
            s1 += __shfl_xor_sync(0xffffffffu, s1, 16);
            s2 += __shfl_xor_sync(0xffffffffu, s2, 16);
            if (lane < 16) {
                rec_sm[rm][u]       = s0;
                rec_sm[rm][u + 128] = s1;
                rec_sm[rm][u + 256] = s2;
            }
        }

        // ---- gate math for row q, step te ----
        if (ga) {
            float z  = sig_mufu(xzv[q] + rz + gbz);
            float rg = sig_mufu(xrv[q] + rr + gbr);
            float hh = tanh_mufu(xhv[q] + rg * (rh + gbh));
            float hn = hh + z * (hpv[q] - hh);
            hpv[q] = hn;
            h_sm[q][gu >> 6][gu & 63] = hn;
            (q ? gor1 : gor0)[(size_t)te * H_ + gu] = hn;
            xzv[q] = nxz; xrv[q] = nxr; xhv[q] = nxh;
        }
        __syncthreads();
    }
}

// ---------------------------------------------------------------------------
extern "C" void kernel_launch(void* const* d_in, const int* in_sizes, int n_in,
                              void* d_out, int out_size)
{
    const float* x  = (const float*)d_in[0];
    const float* W0 = (const float*)d_in[1];
    const float* U0 = (const float*)d_in[2];
    const float* b0 = (const float*)d_in[3];
    const float* W1 = (const float*)d_in[4];
    const float* U1 = (const float*)d_in[5];
    const float* b1 = (const float*)d_in[6];
    float* out = (float*)d_out;

    float *xp, *h0;
    cudaGetSymbolAddress((void**)&xp, g_xp);
    cudaGetSymbolAddress((void**)&h0, g_h0);

    const int PROJ_GRID = 1024;
    const int rpb = BT_ / PROJ_GRID;   // 128 rows per block

    // layer 0
    proj_kernel<<<PROJ_GRID, 256>>>(x, W0, b0, xp, rpb);
    gru_scan<<<B_ / 2, 256>>>(U0, b0 + G_, xp, h0);
    // layer 1
    proj_kernel<<<PROJ_GRID, 256>>>(h0, W1, b1, xp, rpb);
    gru_scan<<<B_ / 2, 256>>>(U1, b1 + G_, xp, out);
}

// round 14
// speedup vs baseline: 1.1858x; 1.1858x over previous
#include <cuda_runtime.h>
#include <cstdint>

#define B_ 256
#define T_ 512
#define D_ 128
#define H_ 128
#define G_ 384          // 3H, gate order z|r|h
#define BT_ (B_*T_)

__device__ float g_xp[(size_t)BT_ * G_];   // 201 MB scratch
__device__ float g_h0[(size_t)BT_ * H_];   // 67 MB scratch

typedef unsigned long long u64;

static __device__ __forceinline__ u64 pack2(float a, float b) {
    u64 r; asm("mov.b64 %0, {%1, %2};" : "=l"(r) : "f"(a), "f"(b)); return r;
}
static __device__ __forceinline__ void unpack2(u64 v, float &a, float &b) {
    asm("mov.b64 {%0, %1}, %2;" : "=f"(a), "=f"(b) : "l"(v));
}
static __device__ __forceinline__ u64 fma2(u64 a, u64 b, u64 c) {
    u64 d; asm("fma.rn.f32x2 %0, %1, %2, %3;" : "=l"(d) : "l"(a), "l"(b), "l"(c)); return d;
}
// MUFU tanh (sm_75+ PTX, not arch-'a' gated)
static __device__ __forceinline__ float tanh_mufu(float x) {
    float r; asm("tanh.approx.f32 %0, %1;" : "=f"(r) : "f"(x)); return r;
}
static __device__ __forceinline__ float sig_mufu(float x) {
    return fmaf(0.5f, tanh_mufu(0.5f * x), 0.5f);
}

// ---------------------------------------------------------------------------
// Projection — R11 version (measured ~291us/layer), with recurrent z/r bias
// folded into the output so the scan needs only the h-gate recurrent bias.
// 256 threads; thread (u, kg) owns gate-triple columns {u,u+128,u+256} over
// its 64-k half; 16 broadcast LDS.128 -> 96 FFMA2 -> 3 shfl.xor(16) -> STG.
// ---------------------------------------------------------------------------
__global__ __launch_bounds__(256, 1)
void proj_kernel(const float* __restrict__ x, const float* __restrict__ W,
                 const float* __restrict__ bin, const float* __restrict__ brec,
                 float* __restrict__ out, int rows_per_block)
{
    __shared__ __align__(16) float x_sm[2][8][D_];
    const int tid  = threadIdx.x;
    const int lane = tid & 31;
    const int kg   = lane >> 4;
    const int u    = (tid >> 5) * 16 + (lane & 15);
    const int kb   = kg * 64;

    u64 w[3][32];
#pragma unroll
    for (int i = 0; i < 32; i++)
#pragma unroll
        for (int c = 0; c < 3; c++)
            w[c][i] = pack2(W[(kb + 2*i) * G_ + u + c*128],
                            W[(kb + 2*i + 1) * G_ + u + c*128]);
    // fold recurrent z/r bias here (h-gate recurrent bias stays in the scan)
    const float b0 = bin[u]       + brec[u];
    const float b1 = bin[u + 128] + brec[u + 128];
    const float b2 = bin[u + 256];

    const int row0 = blockIdx.x * rows_per_block;
    ((float4*)&x_sm[0][0][0])[tid] = ((const float4*)(x + (size_t)row0 * D_))[tid];
    __syncthreads();

    const int iters = rows_per_block / 8;
    int buf = 0;
    for (int it = 0; it < iters; it++) {
        const int rbase = row0 + it * 8;
        float4 nx;
        const bool pre = (it + 1 < iters);
        if (pre)
            nx = ((const float4*)(x + (size_t)(rbase + 8) * D_))[tid];

#pragma unroll
        for (int r = 0; r < 8; r++) {
            u64 a0 = 0, a1 = 0, a2 = 0;
            const float* xs = &x_sm[buf][r][kb];
#pragma unroll
            for (int i2 = 0; i2 < 16; i2++) {
                ulonglong2 hv = *(const ulonglong2*)&xs[4*i2];
                a0 = fma2(hv.x, w[0][2*i2],     a0);
                a0 = fma2(hv.y, w[0][2*i2 + 1], a0);
                a1 = fma2(hv.x, w[1][2*i2],     a1);
                a1 = fma2(hv.y, w[1][2*i2 + 1], a1);
                a2 = fma2(hv.x, w[2][2*i2],     a2);
                a2 = fma2(hv.y, w[2][2*i2 + 1], a2);
            }
            float pa, pb, pc, pd, pe, pf;
            unpack2(a0, pa, pb);
            unpack2(a1, pc, pd);
            unpack2(a2, pe, pf);
            float s0 = pa + pb, s1 = pc + pd, s2 = pe + pf;
            s0 += __shfl_xor_sync(0xffffffffu, s0, 16);
            s1 += __shfl_xor_sync(0xffffffffu, s1, 16);
            s2 += __shfl_xor_sync(0xffffffffu, s2, 16);
            if (lane < 16) {
                float* o = out + (size_t)(rbase + r) * G_;
                o[u]       = s0 + b0;
                o[u + 128] = s1 + b1;
                o[u + 256] = s2 + b2;
            }
        }
        if (pre)
            ((float4*)&x_sm[buf ^ 1][0][0])[tid] = nx;
        __syncthreads();
        buf ^= 1;
    }
}

// ---------------------------------------------------------------------------
// GRU scan, 512 threads (4 warps/SMSP), k split 4-way. Thread (u, kq):
//   kq = lane>>3 (k-quarter), u = warp*8 + lane&7. Owns gate-triple columns
//   {u, u+128, u+256} over its 32-k quarter for BOTH rows (48 weight u64).
// Per row: 8 broadcast LDS.128 -> 48 FFMA2 -> shfl.xor(8)+shfl.xor(16) ->
// gate on lanes kq in {0,2} (row = kq>>1). Same total FMA issue per barrier
// as R12 but 2x the warps per SMSP to hide the serial tail. One bar/step.
// z/r recurrent biases are pre-folded into xp by proj_kernel.
// ---------------------------------------------------------------------------
__global__ __launch_bounds__(512, 1)
void gru_scan(const float* __restrict__ U, const float* __restrict__ brec,
              const float* __restrict__ xp, float* __restrict__ out)
{
    // [buf][row][kq][32 + 4 pad]: kq slices 144B apart -> distinct banks
    __shared__ __align__(16) float h_sm[2][2][4][36];
    const int tid  = threadIdx.x;
    const int lane = tid & 31;
    const int kq   = lane >> 3;                 // 0..3
    const int u    = (tid >> 5) * 8 + (lane & 7);   // 0..127
    const int kb   = kq * 32;

    u64 w[3][16];
#pragma unroll
    for (int i = 0; i < 16; i++)
#pragma unroll
        for (int c = 0; c < 3; c++)
            w[c][i] = pack2(U[(kb + 2*i) * G_ + u + c*128],
                            U[(kb + 2*i + 1) * G_ + u + c*128]);

    const bool gl = (kq & 1) == 0;    // gate lane
    const int  gr = kq >> 1;          // gate row
    const float bh = brec[u + 256];   // h-gate recurrent bias (inside r*(...))
    const int b0 = blockIdx.x * 2;
    const float* exr = xp + (size_t)(b0 + gr) * T_ * G_;
    float* eo = out + (size_t)(b0 + gr) * T_ * H_;
    float hp = 0.0f;

    if (tid < 256)
        h_sm[0][tid >> 7][(tid >> 5) & 3][tid & 31] = 0.0f;
    __syncthreads();

    for (int t = 0; t < T_; t++) {
        const int buf = t & 1;
        // xp for this step, loaded at the top: DRAM latency hides under the
        // ~1150-cycle FMA block below (no cross-step live registers).
        float xz = 0.f, xr_ = 0.f, xh = 0.f;
        if (gl) {
            const float* xn = exr + (size_t)t * G_;
            xz = xn[u]; xr_ = xn[u + 128]; xh = xn[u + 256];
        }

#pragma unroll
        for (int r = 0; r < 2; r++) {
            u64 a0 = 0, a1 = 0, a2 = 0;
            const float* hs = &h_sm[buf][r][kq][0];
#pragma unroll
            for (int i2 = 0; i2 < 8; i2++) {
                ulonglong2 hv = *(const ulonglong2*)&hs[4*i2];
                a0 = fma2(hv.x, w[0][2*i2],     a0);
                a0 = fma2(hv.y, w[0][2*i2 + 1], a0);
                a1 = fma2(hv.x, w[1][2*i2],     a1);
                a1 = fma2(hv.y, w[1][2*i2 + 1], a1);
                a2 = fma2(hv.x, w[2][2*i2],     a2);
                a2 = fma2(hv.y, w[2][2*i2 + 1], a2);
            }
            float pa, pb, pc, pd, pe, pf;
            unpack2(a0, pa, pb);
            unpack2(a1, pc, pd);
            unpack2(a2, pe, pf);
            float s0 = pa + pb, s1 = pc + pd, s2 = pe + pf;
            s0 += __shfl_xor_sync(0xffffffffu, s0, 8);
            s1 += __shfl_xor_sync(0xffffffffu, s1, 8);
            s2 += __shfl_xor_sync(0xffffffffu, s2, 8);
            s0 += __shfl_xor_sync(0xffffffffu, s0, 16);
            s1 += __shfl_xor_sync(0xffffffffu, s1, 16);
            s2 += __shfl_xor_sync(0xffffffffu, s2, 16);

            if (gl && gr == r) {
                float z  = sig_mufu(xz + s0);          // z/r bias pre-folded
                float rg = sig_mufu(xr_ + s1);
                float hh = tanh_mufu(xh + rg * (s2 + bh));
                float hn = hh + z * (hp - hh);
                hp = hn;
                h_sm[buf ^ 1][r][u >> 5][u & 31] = hn;
                eo[(size_t)t * H_ + u] = hn;
            }
        }
        __syncthreads();
    }
}

// ---------------------------------------------------------------------------
extern "C" void kernel_launch(void* const* d_in, const int* in_sizes, int n_in,
                              void* d_out, int out_size)
{
    const float* x  = (const float*)d_in[0];
    const float* W0 = (const float*)d_in[1];
    const float* U0 = (const float*)d_in[2];
    const float* b0 = (const float*)d_in[3];
    const float* W1 = (const float*)d_in[4];
    const float* U1 = (const float*)d_in[5];
    const float* b1 = (const float*)d_in[6];
    float* out = (float*)d_out;

    float *xp, *h0;
    cudaGetSymbolAddress((void**)&xp, g_xp);
    cudaGetSymbolAddress((void**)&h0, g_h0);

    const int PROJ_GRID = 1024;
    const int rpb = BT_ / PROJ_GRID;   // 128 rows per block

    // layer 0
    proj_kernel<<<PROJ_GRID, 256>>>(x, W0, b0, b0 + G_, xp, rpb);
    gru_scan<<<B_ / 2, 512>>>(U0, b0 + G_, xp, h0);
    // layer 1
    proj_kernel<<<PROJ_GRID, 256>>>(h0, W1, b1, b1 + G_, xp, rpb);
    gru_scan<<<B_ / 2, 512>>>(U1, b1 + G_, xp, out);
}

// round 15
// speedup vs baseline: 1.7030x; 1.4362x over previous
#include <cuda_runtime.h>
#include <cstdint>

#define B_ 256
#define T_ 512
#define D_ 128
#define H_ 128
#define G_ 384          // 3H, gate order z|r|h
#define BT_ (B_*T_)

__device__ float g_xp[(size_t)BT_ * G_];   // 201 MB scratch
__device__ float g_h0[(size_t)BT_ * H_];   // 67 MB scratch

typedef unsigned long long u64;

static __device__ __forceinline__ u64 pack2(float a, float b) {
    u64 r; asm("mov.b64 %0, {%1, %2};" : "=l"(r) : "f"(a), "f"(b)); return r;
}
static __device__ __forceinline__ void unpack2(u64 v, float &a, float &b) {
    asm("mov.b64 {%0, %1}, %2;" : "=f"(a), "=f"(b) : "l"(v));
}
static __device__ __forceinline__ u64 fma2(u64 a, u64 b, u64 c) {
    u64 d; asm("fma.rn.f32x2 %0, %1, %2, %3;" : "=l"(d) : "l"(a), "l"(b), "l"(c)); return d;
}
// MUFU tanh (sm_75+ PTX, not arch-'a' gated)
static __device__ __forceinline__ float tanh_mufu(float x) {
    float r; asm("tanh.approx.f32 %0, %1;" : "=f"(r) : "f"(x)); return r;
}
static __device__ __forceinline__ float sig_mufu(float x) {
    return fmaf(0.5f, tanh_mufu(0.5f * x), 0.5f);
}

// ---------------------------------------------------------------------------
// Projection — VERBATIM R12 (measured ~286us/layer): 256 threads; thread
// (u, kg) owns gate-triple columns {u, u+128, u+256} over its 64-k half.
// Per row: 16 broadcast LDS.128 -> 96 FFMA2 -> 3 shfl.xor(16) -> lane<16 STG.
// ---------------------------------------------------------------------------
__global__ __launch_bounds__(256, 1)
void proj_kernel(const float* __restrict__ x, const float* __restrict__ W,
                 const float* __restrict__ bin, float* __restrict__ out,
                 int rows_per_block)
{
    __shared__ __align__(16) float x_sm[2][8][D_];
    const int tid  = threadIdx.x;
    const int lane = tid & 31;
    const int kg   = lane >> 4;
    const int u    = (tid >> 5) * 16 + (lane & 15);
    const int kb   = kg * 64;

    u64 w[3][32];
#pragma unroll
    for (int i = 0; i < 32; i++)
#pragma unroll
        for (int c = 0; c < 3; c++)
            w[c][i] = pack2(W[(kb + 2*i) * G_ + u + c*128],
                            W[(kb + 2*i + 1) * G_ + u + c*128]);
    const float b0 = bin[u];
    const float b1 = bin[u + 128];
    const float b2 = bin[u + 256];

    const int row0 = blockIdx.x * rows_per_block;
    ((float4*)&x_sm[0][0][0])[tid] = ((const float4*)(x + (size_t)row0 * D_))[tid];
    __syncthreads();

    const int iters = rows_per_block / 8;
    int buf = 0;
    for (int it = 0; it < iters; it++) {
        const int rbase = row0 + it * 8;
        float4 nx;
        const bool pre = (it + 1 < iters);
        if (pre)
            nx = ((const float4*)(x + (size_t)(rbase + 8) * D_))[tid];

#pragma unroll
        for (int r = 0; r < 8; r++) {
            u64 a0 = 0, a1 = 0, a2 = 0;
            const float* xs = &x_sm[buf][r][kb];
#pragma unroll
            for (int i2 = 0; i2 < 16; i2++) {
                ulonglong2 hv = *(const ulonglong2*)&xs[4*i2];
                a0 = fma2(hv.x, w[0][2*i2],     a0);
                a0 = fma2(hv.y, w[0][2*i2 + 1], a0);
                a1 = fma2(hv.x, w[1][2*i2],     a1);
                a1 = fma2(hv.y, w[1][2*i2 + 1], a1);
                a2 = fma2(hv.x, w[2][2*i2],     a2);
                a2 = fma2(hv.y, w[2][2*i2 + 1], a2);
            }
            float pa, pb, pc, pd, pe, pf;
            unpack2(a0, pa, pb);
            unpack2(a1, pc, pd);
            unpack2(a2, pe, pf);
            float s0 = pa + pb, s1 = pc + pd, s2 = pe + pf;
            s0 += __shfl_xor_sync(0xffffffffu, s0, 16);
            s1 += __shfl_xor_sync(0xffffffffu, s1, 16);
            s2 += __shfl_xor_sync(0xffffffffu, s2, 16);
            if (lane < 16) {
                float* o = out + (size_t)(rbase + r) * G_;
                o[u]       = s0 + b0;
                o[u + 128] = s1 + b1;
                o[u + 256] = s2 + b2;
            }
        }
        if (pre)
            ((float4*)&x_sm[buf ^ 1][0][0])[tid] = nx;
        __syncthreads();
        buf ^= 1;
    }
}

// ---------------------------------------------------------------------------
// GRU scan — R12 shape (256 thr, 2 rows/CTA, U in regs, 1 bar/step), with the
// step interior interleaved: matvec r0 -> reduce+gates r0 (kg==0 lanes, MUFU
// latency hidden under...) -> matvec r1 (576-cyc FMA block) -> store h0 ->
// reduce+gates+store r1 -> bar. Exposed tail = r1's chain only.
// ---------------------------------------------------------------------------
__global__ __launch_bounds__(256, 1)
void gru_scan(const float* __restrict__ U, const float* __restrict__ brec,
              const float* __restrict__ xp, float* __restrict__ out)
{
    __shared__ __align__(16) float h_sm[2][2][2][68];  // [buf][row][kg][pad]
    const int tid  = threadIdx.x;
    const int lane = tid & 31;
    const int kg   = lane >> 4;
    const int u    = (tid >> 5) * 16 + (lane & 15);
    const int kb   = kg * 64;

    u64 w[3][32];
#pragma unroll
    for (int i = 0; i < 32; i++)
#pragma unroll
        for (int c = 0; c < 3; c++)
            w[c][i] = pack2(U[(kb + 2*i) * G_ + u + c*128],
                            U[(kb + 2*i + 1) * G_ + u + c*128]);
    const float bz = brec[u], br_ = brec[u + 128], bh = brec[u + 256];

    const int row = kg;                 // this thread's gate row
    const int b0  = blockIdx.x * 2;
    const float* exr = xp + (size_t)(b0 + row) * T_ * G_;
    float* eo = out + (size_t)(b0 + row) * T_ * H_;

    float xz  = exr[u];
    float xr_ = exr[u + 128];
    float xh  = exr[u + 256];
    float hp  = 0.0f;

    if (tid < 128) {
        h_sm[0][0][tid >> 6][tid & 63] = 0.0f;
        h_sm[0][1][tid >> 6][tid & 63] = 0.0f;
    }
    __syncthreads();

    for (int t = 0; t < T_; t++) {
        const int buf = t & 1;
        float nxz = 0.f, nxr = 0.f, nxh = 0.f;
        if (t + 1 < T_) {
            const float* xn = exr + (size_t)(t + 1) * G_;
            nxz = xn[u]; nxr = xn[u + 128]; nxh = xn[u + 256];
        }

        // ---- matvec row 0 ----
        u64 a0 = 0, a1 = 0, a2 = 0;
        {
            const float* hs = &h_sm[buf][0][kg][0];
#pragma unroll
            for (int i2 = 0; i2 < 16; i2++) {
                ulonglong2 hv = *(const ulonglong2*)&hs[4*i2];
                a0 = fma2(hv.x, w[0][2*i2], a0);
                a0 = fma2(hv.y, w[0][2*i2 + 1], a0);
                a1 = fma2(hv.x, w[1][2*i2], a1);
                a1 = fma2(hv.y, w[1][2*i2 + 1], a1);
                a2 = fma2(hv.x, w[2][2*i2], a2);
                a2 = fma2(hv.y, w[2][2*i2 + 1], a2);
            }
        }
        // ---- reduce + gates row 0 (kg==0 lanes own row 0) ----
        float hn0 = 0.0f;
        {
            float pa, pb, pc, pd, pe, pf;
            unpack2(a0, pa, pb); unpack2(a1, pc, pd); unpack2(a2, pe, pf);
            float s0 = pa + pb, s1 = pc + pd, s2 = pe + pf;
            s0 += __shfl_xor_sync(0xffffffffu, s0, 16);
            s1 += __shfl_xor_sync(0xffffffffu, s1, 16);
            s2 += __shfl_xor_sync(0xffffffffu, s2, 16);
            if (kg == 0) {
                float z  = sig_mufu(xz + s0 + bz);
                float rg = sig_mufu(xr_ + s1 + br_);
                float hh = tanh_mufu(xh + rg * (s2 + bh));
                hn0 = hh + z * (hp - hh);
            }
        }

        // ---- matvec row 1 (hides row 0's shfl/MUFU latency) ----
        u64 c0 = 0, c1 = 0, c2 = 0;
        {
            const float* hs = &h_sm[buf][1][kg][0];
#pragma unroll
            for (int i2 = 0; i2 < 16; i2++) {
                ulonglong2 hv = *(const ulonglong2*)&hs[4*i2];
                c0 = fma2(hv.x, w[0][2*i2], c0);
                c0 = fma2(hv.y, w[0][2*i2 + 1], c0);
                c1 = fma2(hv.x, w[1][2*i2], c1);
                c1 = fma2(hv.y, w[1][2*i2 + 1], c1);
                c2 = fma2(hv.x, w[2][2*i2], c2);
                c2 = fma2(hv.y, w[2][2*i2 + 1], c2);
            }
        }
        // ---- store h0 results (after r1 FMA block) ----
        if (kg == 0) {
            hp = hn0;
            h_sm[buf ^ 1][0][u >> 6][u & 63] = hn0;
            eo[(size_t)t * H_ + u] = hn0;
        }
        // ---- reduce + gates + store row 1 (kg==1 lanes own row 1) ----
        {
            float pa, pb, pc, pd, pe, pf;
            unpack2(c0, pa, pb); unpack2(c1, pc, pd); unpack2(c2, pe, pf);
            float s0 = pa + pb, s1 = pc + pd, s2 = pe + pf;
            s0 += __shfl_xor_sync(0xffffffffu, s0, 16);
            s1 += __shfl_xor_sync(0xffffffffu, s1, 16);
            s2 += __shfl_xor_sync(0xffffffffu, s2, 16);
            if (kg == 1) {
                float z  = sig_mufu(xz + s0 + bz);
                float rg = sig_mufu(xr_ + s1 + br_);
                float hh = tanh_mufu(xh + rg * (s2 + bh));
                float hn = hh + z * (hp - hh);
                hp = hn;
                h_sm[buf ^ 1][1][u >> 6][u & 63] = hn;
                eo[(size_t)t * H_ + u] = hn;
            }
        }
        xz = nxz; xr_ = nxr; xh = nxh;
        __syncthreads();
    }
}

// ---------------------------------------------------------------------------
extern "C" void kernel_launch(void* const* d_in, const int* in_sizes, int n_in,
                              void* d_out, int out_size)
{
    const float* x  = (const float*)d_in[0];
    const float* W0 = (const float*)d_in[1];
    const float* U0 = (const float*)d_in[2];
    const float* b0 = (const float*)d_in[3];
    const float* W1 = (const float*)d_in[4];
    const float* U1 = (const float*)d_in[5];
    const float* b1 = (const float*)d_in[6];
    float* out = (float*)d_out;

    float *xp, *h0;
    cudaGetSymbolAddress((void**)&xp, g_xp);
    cudaGetSymbolAddress((void**)&h0, g_h0);

    const int PROJ_GRID = 1024;
    const int rpb = BT_ / PROJ_GRID;   // 128 rows per block

    // layer 0
    proj_kernel<<<PROJ_GRID, 256>>>(x, W0, b0, xp, rpb);
    gru_scan<<<B_ / 2, 256>>>(U0, b0 + G_, xp, h0);
    // layer 1
    proj_kernel<<<PROJ_GRID, 256>>>(h0, W1, b1, xp, rpb);
    gru_scan<<<B_ / 2, 256>>>(U1, b1 + G_, xp, out);
}